// round 1
// baseline (speedup 1.0000x reference)
#include <cuda_runtime.h>
#include <math.h>
#include <float.h>

#define NB 8
#define NM 64
#define NA 49104
#define NC 80
#define TILE 256
#define THREADS 256

// per-image accumulators (scratch; no allocations allowed)
__device__ double g_cls[NB];
__device__ double g_reg[NB];
__device__ int    g_npos[NB];

__global__ void fl_init_kernel() {
    int i = threadIdx.x;
    if (i < NB) { g_cls[i] = 0.0; g_reg[i] = 0.0; g_npos[i] = 0; }
}

__global__ __launch_bounds__(THREADS)
void fl_main_kernel(const float* __restrict__ boxes,      // [B,M,4] (x1,y1,x2,y2)
                    const int*   __restrict__ labels,     // [B,M]
                    const float* __restrict__ anchors,    // [1,A,4] (y1,x1,y2,x2)
                    const float* __restrict__ cls,        // [B,A,C]
                    const float* __restrict__ reg)        // [B,A,4]
{
    __shared__ float4 s_box[NM];
    __shared__ int    s_lab[NM];
    __shared__ int    s_tc[TILE];
    __shared__ float  s_c[THREADS / 32];
    __shared__ float  s_r[THREADS / 32];
    __shared__ int    s_p[THREADS / 32];

    const int b     = blockIdx.y;
    const int abase = blockIdx.x * TILE;
    const int t     = threadIdx.x;

    if (t < NM) {
        s_box[t] = ((const float4*)boxes)[b * NM + t];
        s_lab[t] = labels[b * NM + t];
    }
    __syncthreads();

    const int a = abase + t;
    float my_reg = 0.0f;
    int   my_pos = 0;

    if (a < NA) {
        float4 an = ((const float4*)anchors)[a];   // y1,x1,y2,x2
        const float ay1 = an.x, ax1 = an.y, ay2 = an.z, ax2 = an.w;
        const float a_area = (ay2 - ay1) * (ax2 - ax1);

        float best = -2.0f; int bi = 0;
        #pragma unroll 8
        for (int m = 0; m < NM; m++) {
            float4 bx = s_box[m];                  // x1,y1,x2,y2
            float iou = -1.0f;
            if (s_lab[m] != 0) {
                float iw = fminf(ax2, bx.z) - fmaxf(ax1, bx.x);
                float ih = fminf(ay2, bx.w) - fmaxf(ay1, bx.y);
                iw = fmaxf(iw, 0.0f); ih = fmaxf(ih, 0.0f);
                float inter = iw * ih;
                float barea = (bx.z - bx.x) * (bx.w - bx.y);
                float ua = fmaxf(a_area + barea - inter, 1e-8f);
                iou = inter / ua;
            }
            if (iou > best) { best = iou; bi = m; }  // strict >: first max (argmax)
        }

        float4 ab = s_box[bi];
        int    al = s_lab[bi] - 1;
        float  bw = ab.z - ab.x, bh = ab.w - ab.y;
        bool   big = (bw * bh) > 100.0f;
        bool   pos = big ? (best >= 0.5f) : (best >= 0.15f);
        s_tc[t] = pos ? al : -1;
        my_pos = pos ? 1 : 0;

        if (pos) {
            float gw = bw, gh = bh;
            float gcx = ab.x + 0.5f * gw, gcy = ab.y + 0.5f * gh;
            gw = fmaxf(gw, 1.0f); gh = fmaxf(gh, 1.0f);
            float aw = ax2 - ax1, ah = ay2 - ay1;
            float acx = ax1 + 0.5f * aw, acy = ay1 + 0.5f * ah;
            float tt0 = (gcy - acy) / ah;
            float tt1 = (gcx - acx) / aw;
            float tt2 = logf(gh / ah);
            float tt3 = logf(gw / aw);
            float4 r = ((const float4*)reg)[(size_t)b * NA + a];
            float d;
            d = fabsf(tt0 - r.x); my_reg += (d <= 1.0f/9.0f) ? 4.5f*d*d : d - 0.5f/9.0f;
            d = fabsf(tt1 - r.y); my_reg += (d <= 1.0f/9.0f) ? 4.5f*d*d : d - 0.5f/9.0f;
            d = fabsf(tt2 - r.z); my_reg += (d <= 1.0f/9.0f) ? 4.5f*d*d : d - 0.5f/9.0f;
            d = fabsf(tt3 - r.w); my_reg += (d <= 1.0f/9.0f) ? 4.5f*d*d : d - 0.5f/9.0f;
        }
    } else {
        s_tc[t] = -1;
    }
    __syncthreads();

    // ---- classification focal loss over this tile (coalesced float4 stream) ----
    float csum = 0.0f;
    {
        int maxa = NA - abase; if (maxa > TILE) maxa = TILE;
        const int nvec = maxa * (NC / 4);           // float4 count (80 % 4 == 0, no straddle)
        const float4* cptr = (const float4*)(cls + ((size_t)b * NA + abase) * NC);
        for (int i = t; i < nvec; i += THREADS) {
            const int anc = i / (NC / 4);
            const int cb  = (i - anc * (NC / 4)) * 4;
            const int tc  = s_tc[anc];
            float4 v = cptr[i];
            float vv[4] = {v.x, v.y, v.z, v.w};
            #pragma unroll
            for (int k = 0; k < 4; k++) {
                float p = fminf(fmaxf(vv[k], 1e-4f), 1.0f - 1e-4f);
                if (cb + k == tc) {
                    float om = 1.0f - p;
                    csum += 0.25f * om * om * (-__logf(p));
                } else {
                    csum += 0.75f * p * p * (-__logf(1.0f - p));
                }
            }
        }
    }

    // ---- block reduction: csum, my_reg, my_pos ----
    #pragma unroll
    for (int o = 16; o; o >>= 1) {
        csum   += __shfl_down_sync(0xFFFFFFFFu, csum,   o);
        my_reg += __shfl_down_sync(0xFFFFFFFFu, my_reg, o);
        my_pos += __shfl_down_sync(0xFFFFFFFFu, my_pos, o);
    }
    const int wid = t >> 5, lid = t & 31;
    if (lid == 0) { s_c[wid] = csum; s_r[wid] = my_reg; s_p[wid] = my_pos; }
    __syncthreads();
    if (wid == 0) {
        const int nw = THREADS / 32;
        float c = (lid < nw) ? s_c[lid] : 0.0f;
        float r = (lid < nw) ? s_r[lid] : 0.0f;
        int   p = (lid < nw) ? s_p[lid] : 0;
        #pragma unroll
        for (int o = 16; o; o >>= 1) {
            c += __shfl_down_sync(0xFFFFFFFFu, c, o);
            r += __shfl_down_sync(0xFFFFFFFFu, r, o);
            p += __shfl_down_sync(0xFFFFFFFFu, p, o);
        }
        if (lid == 0) {
            atomicAdd(&g_cls[b], (double)c);
            atomicAdd(&g_reg[b], (double)r);
            atomicAdd(&g_npos[b], p);
        }
    }
}

__global__ void fl_finalize_kernel(float* __restrict__ out) {
    int i = threadIdx.x;
    double c = 0.0, r = 0.0;
    if (i < NB) {
        int np = g_npos[i];
        double den = (double)(np > 1 ? np : 1);
        c = g_cls[i] / den;
        r = (np > 0) ? (g_reg[i] / (4.0 * den)) : 0.0;
    }
    #pragma unroll
    for (int o = 16; o; o >>= 1) {
        c += __shfl_down_sync(0xFFFFFFFFu, c, o);
        r += __shfl_down_sync(0xFFFFFFFFu, r, o);
    }
    if (i == 0) {
        out[0] = (float)(c / (double)NB);
        out[1] = (float)(r / (double)NB * 50.0);
    }
}

extern "C" void kernel_launch(void* const* d_in, const int* in_sizes, int n_in,
                              void* d_out, int out_size) {
    const float* boxes   = (const float*)d_in[0];
    const int*   labels  = (const int*)  d_in[1];
    const float* anchors = (const float*)d_in[2];
    const float* cls     = (const float*)d_in[3];
    const float* reg     = (const float*)d_in[4];
    float* out = (float*)d_out;

    fl_init_kernel<<<1, 32>>>();
    dim3 grid((NA + TILE - 1) / TILE, NB);
    fl_main_kernel<<<grid, THREADS>>>(boxes, labels, anchors, cls, reg);
    fl_finalize_kernel<<<1, 32>>>(out);
}

// round 2
// speedup vs baseline: 1.0441x; 1.0441x over previous
#include <cuda_runtime.h>
#include <math.h>

#define NB 8
#define NM 64
#define NA 49104
#define NC 80
#define THREADS 256
#define GX 148                       // stream blocks per image (one full wave at occ 8)
#define VEC (NA * (NC / 4))          // float4s per image = 982080
#define STRIDE (GX * THREADS)

// per-image accumulators (scratch; zero at module load, reset by finalize)
__device__ double g_cls[NB];
__device__ double g_reg[NB];
__device__ int    g_npos[NB];

// ---------------------------------------------------------------------------
// Kernel 1: anchor assignment + regression loss + sparse positive corrections
// ---------------------------------------------------------------------------
__global__ __launch_bounds__(THREADS)
void fl_assign_kernel(const float* __restrict__ boxes,      // [B,M,4] (x1,y1,x2,y2)
                      const int*   __restrict__ labels,     // [B,M]
                      const float* __restrict__ anchors,    // [1,A,4] (y1,x1,y2,x2)
                      const float* __restrict__ cls,        // [B,A,C]
                      const float* __restrict__ reg)        // [B,A,4]
{
    __shared__ float4 s_box[NM];
    __shared__ float  s_barea[NM];
    __shared__ int    s_lab[NM];
    __shared__ float  s_c[THREADS / 32];
    __shared__ float  s_r[THREADS / 32];
    __shared__ int    s_p[THREADS / 32];

    const int b = blockIdx.y;
    const int t = threadIdx.x;

    if (t < NM) {
        float4 bx = ((const float4*)boxes)[b * NM + t];
        s_box[t]   = bx;
        s_barea[t] = (bx.z - bx.x) * (bx.w - bx.y);
        s_lab[t]   = labels[b * NM + t];
    }
    __syncthreads();

    const int a = blockIdx.x * THREADS + t;
    float my_reg = 0.0f, my_corr = 0.0f;
    int   my_pos = 0;

    if (a < NA) {
        float4 an = ((const float4*)anchors)[a];   // y1,x1,y2,x2
        const float ay1 = an.x, ax1 = an.y, ay2 = an.z, ax2 = an.w;
        const float a_area = (ay2 - ay1) * (ax2 - ax1);

        float best = -2.0f; int bi = 0;
        #pragma unroll 8
        for (int m = 0; m < NM; m++) {
            float4 bx = s_box[m];                  // x1,y1,x2,y2
            float iou = -1.0f;
            if (s_lab[m] != 0) {
                float iw = fminf(ax2, bx.z) - fmaxf(ax1, bx.x);
                float ih = fminf(ay2, bx.w) - fmaxf(ay1, bx.y);
                iw = fmaxf(iw, 0.0f); ih = fmaxf(ih, 0.0f);
                float inter = iw * ih;
                float ua = fmaxf(a_area + s_barea[m] - inter, 1e-8f);
                iou = inter / ua;
            }
            if (iou > best) { best = iou; bi = m; }  // strict >: first max (argmax)
        }

        float4 ab = s_box[bi];
        float  bw = ab.z - ab.x, bh = ab.w - ab.y;
        bool   big = (bw * bh) > 100.0f;
        bool   pos = big ? (best >= 0.5f) : (best >= 0.15f);

        if (pos) {
            my_pos = 1;
            // --- regression smooth-L1 ---
            float gcx = ab.x + 0.5f * bw, gcy = ab.y + 0.5f * bh;
            float gw = fmaxf(bw, 1.0f), gh = fmaxf(bh, 1.0f);
            float aw = ax2 - ax1, ah = ay2 - ay1;
            float acx = ax1 + 0.5f * aw, acy = ay1 + 0.5f * ah;
            float tt0 = (gcy - acy) / ah;
            float tt1 = (gcx - acx) / aw;
            float tt2 = logf(gh / ah);
            float tt3 = logf(gw / aw);
            float4 r = ((const float4*)reg)[(size_t)b * NA + a];
            float d;
            d = fabsf(tt0 - r.x); my_reg += (d <= 1.0f/9.0f) ? 4.5f*d*d : d - 0.5f/9.0f;
            d = fabsf(tt1 - r.y); my_reg += (d <= 1.0f/9.0f) ? 4.5f*d*d : d - 0.5f/9.0f;
            d = fabsf(tt2 - r.z); my_reg += (d <= 1.0f/9.0f) ? 4.5f*d*d : d - 0.5f/9.0f;
            d = fabsf(tt3 - r.w); my_reg += (d <= 1.0f/9.0f) ? 4.5f*d*d : d - 0.5f/9.0f;

            // --- sparse classification correction for the target class ---
            int al = s_lab[bi] - 1;                  // in [0, NC)
            float v = cls[((size_t)b * NA + a) * NC + al];
            float p = fminf(fmaxf(v, 1e-4f), 1.0f - 1e-4f);
            float om = 1.0f - p;
            float pos_term = 0.25f * om * om * (-__logf(p));
            float neg_term = 0.75f * p  * p  * (-__logf(om));
            my_corr = pos_term - neg_term;           // stream kernel already added neg_term
        }
    }

    // ---- block reduction ----
    #pragma unroll
    for (int o = 16; o; o >>= 1) {
        my_corr += __shfl_down_sync(0xFFFFFFFFu, my_corr, o);
        my_reg  += __shfl_down_sync(0xFFFFFFFFu, my_reg,  o);
        my_pos  += __shfl_down_sync(0xFFFFFFFFu, my_pos,  o);
    }
    const int wid = t >> 5, lid = t & 31;
    if (lid == 0) { s_c[wid] = my_corr; s_r[wid] = my_reg; s_p[wid] = my_pos; }
    __syncthreads();
    if (wid == 0) {
        const int nw = THREADS / 32;
        float c = (lid < nw) ? s_c[lid] : 0.0f;
        float r = (lid < nw) ? s_r[lid] : 0.0f;
        int   p = (lid < nw) ? s_p[lid] : 0;
        #pragma unroll
        for (int o = 16; o; o >>= 1) {
            c += __shfl_down_sync(0xFFFFFFFFu, c, o);
            r += __shfl_down_sync(0xFFFFFFFFu, r, o);
            p += __shfl_down_sync(0xFFFFFFFFu, p, o);
        }
        if (lid == 0) {
            if (c != 0.0f) atomicAdd(&g_cls[b], (double)c);
            if (r != 0.0f) atomicAdd(&g_reg[b], (double)r);
            if (p)         atomicAdd(&g_npos[b], p);
        }
    }
}

// ---------------------------------------------------------------------------
// Kernel 2: pure negative-term focal stream over [B,A,C] — HBM-bound
// ---------------------------------------------------------------------------
__global__ __launch_bounds__(THREADS)
void fl_stream_kernel(const float* __restrict__ cls)
{
    __shared__ float s_w[THREADS / 32];
    const int b = blockIdx.y;
    const float4* __restrict__ cp = (const float4*)(cls + (size_t)b * NA * NC);
    const int tid = blockIdx.x * THREADS + threadIdx.x;

    float s0 = 0.0f, s1 = 0.0f, s2 = 0.0f, s3 = 0.0f;
    #pragma unroll 4
    for (int i = tid; i < VEC; i += STRIDE) {
        float4 v = cp[i];
        float p0 = fminf(fmaxf(v.x, 1e-4f), 1.0f - 1e-4f);
        float p1 = fminf(fmaxf(v.y, 1e-4f), 1.0f - 1e-4f);
        float p2 = fminf(fmaxf(v.z, 1e-4f), 1.0f - 1e-4f);
        float p3 = fminf(fmaxf(v.w, 1e-4f), 1.0f - 1e-4f);
        float l0 = __logf(1.0f - p0);
        float l1 = __logf(1.0f - p1);
        float l2 = __logf(1.0f - p2);
        float l3 = __logf(1.0f - p3);
        s0 = fmaf(p0 * p0 * l0, -0.75f, s0);
        s1 = fmaf(p1 * p1 * l1, -0.75f, s1);
        s2 = fmaf(p2 * p2 * l2, -0.75f, s2);
        s3 = fmaf(p3 * p3 * l3, -0.75f, s3);
    }
    float csum = (s0 + s1) + (s2 + s3);

    #pragma unroll
    for (int o = 16; o; o >>= 1)
        csum += __shfl_down_sync(0xFFFFFFFFu, csum, o);
    const int wid = threadIdx.x >> 5, lid = threadIdx.x & 31;
    if (lid == 0) s_w[wid] = csum;
    __syncthreads();
    if (wid == 0) {
        const int nw = THREADS / 32;
        float c = (lid < nw) ? s_w[lid] : 0.0f;
        #pragma unroll
        for (int o = 16; o; o >>= 1)
            c += __shfl_down_sync(0xFFFFFFFFu, c, o);
        if (lid == 0) atomicAdd(&g_cls[b], (double)c);
    }
}

// ---------------------------------------------------------------------------
// Kernel 3: finalize (and reset accumulators for the next replay)
// ---------------------------------------------------------------------------
__global__ void fl_finalize_kernel(float* __restrict__ out) {
    int i = threadIdx.x;
    double c = 0.0, r = 0.0;
    if (i < NB) {
        int np = g_npos[i];
        double den = (double)(np > 1 ? np : 1);
        c = g_cls[i] / den;
        r = (np > 0) ? (g_reg[i] / (4.0 * den)) : 0.0;
        g_cls[i] = 0.0; g_reg[i] = 0.0; g_npos[i] = 0;   // reset for next replay
    }
    #pragma unroll
    for (int o = 16; o; o >>= 1) {
        c += __shfl_down_sync(0xFFFFFFFFu, c, o);
        r += __shfl_down_sync(0xFFFFFFFFu, r, o);
    }
    if (i == 0) {
        out[0] = (float)(c / (double)NB);
        out[1] = (float)(r / (double)NB * 50.0);
    }
}

extern "C" void kernel_launch(void* const* d_in, const int* in_sizes, int n_in,
                              void* d_out, int out_size) {
    const float* boxes   = (const float*)d_in[0];
    const int*   labels  = (const int*)  d_in[1];
    const float* anchors = (const float*)d_in[2];
    const float* cls     = (const float*)d_in[3];
    const float* reg     = (const float*)d_in[4];
    float* out = (float*)d_out;

    dim3 ag((NA + THREADS - 1) / THREADS, NB);
    fl_assign_kernel<<<ag, THREADS>>>(boxes, labels, anchors, cls, reg);
    dim3 sg(GX, NB);
    fl_stream_kernel<<<sg, THREADS>>>(cls);
    fl_finalize_kernel<<<1, 32>>>(out);
}

// round 3
// speedup vs baseline: 2.1379x; 2.0476x over previous
#include <cuda_runtime.h>
#include <math.h>

#define NB 8
#define NM 64
#define NA 49104
#define NC 80
#define THREADS 256
#define NA_TILES 192                 // ceil(NA / THREADS)
#define NAB (NA_TILES * NB)          // 1536 assign blocks
#define NSPI 148                     // stream blocks per image
#define NSB (NSPI * NB)              // 1184 stream blocks
#define TOTB (NAB + NSB)             // 2720
#define VEC (NA * (NC / 4))          // float4s per image = 982080
#define SSTRIDE (NSPI * THREADS)

// per-image accumulators (zero at module load; finalize resets for next replay)
__device__ double g_cls[NB];
__device__ double g_reg[NB];
__device__ int    g_npos[NB];

__device__ __forceinline__ void block_reduce_commit(float c, float r, int p, int b,
                                                    float* s_c, float* s_r, int* s_p) {
    #pragma unroll
    for (int o = 16; o; o >>= 1) {
        c += __shfl_down_sync(0xFFFFFFFFu, c, o);
        r += __shfl_down_sync(0xFFFFFFFFu, r, o);
        p += __shfl_down_sync(0xFFFFFFFFu, p, o);
    }
    const int wid = threadIdx.x >> 5, lid = threadIdx.x & 31;
    if (lid == 0) { s_c[wid] = c; s_r[wid] = r; s_p[wid] = p; }
    __syncthreads();
    if (wid == 0) {
        const int nw = THREADS / 32;
        c = (lid < nw) ? s_c[lid] : 0.0f;
        r = (lid < nw) ? s_r[lid] : 0.0f;
        p = (lid < nw) ? s_p[lid] : 0;
        #pragma unroll
        for (int o = 16; o; o >>= 1) {
            c += __shfl_down_sync(0xFFFFFFFFu, c, o);
            r += __shfl_down_sync(0xFFFFFFFFu, r, o);
            p += __shfl_down_sync(0xFFFFFFFFu, p, o);
        }
        if (lid == 0) {
            if (c != 0.0f) atomicAdd(&g_cls[b], (double)c);
            if (r != 0.0f) atomicAdd(&g_reg[b], (double)r);
            if (p)         atomicAdd(&g_npos[b], p);
        }
    }
}

__global__ __launch_bounds__(THREADS)
void fl_fused_kernel(const float* __restrict__ boxes,      // [B,M,4] (x1,y1,x2,y2)
                     const int*   __restrict__ labels,     // [B,M]
                     const float* __restrict__ anchors,    // [1,A,4] (y1,x1,y2,x2)
                     const float* __restrict__ cls,        // [B,A,C]
                     const float* __restrict__ reg)        // [B,A,4]
{
    __shared__ float4 s_box[NM];
    __shared__ float  s_barea[NM];
    __shared__ int    s_lab[NM];
    __shared__ float  s_c[THREADS / 32];
    __shared__ float  s_r[THREADS / 32];
    __shared__ int    s_p[THREADS / 32];

    const int gid = blockIdx.x;
    const int t   = threadIdx.x;

    // interleave roles so assign (issue-bound) and stream (DRAM-bound) overlap
    int role, idx;
    if (gid < 2 * NSB) { role = gid & 1; idx = gid >> 1; }
    else               { role = 0;       idx = NSB + (gid - 2 * NSB); }

    if (role == 1) {
        // ================= STREAM: negative focal term over [A,C] =================
        const int b   = idx / NSPI;
        const int blk = idx - b * NSPI;
        const float4* __restrict__ cp = (const float4*)(cls + (size_t)b * NA * NC);
        const int tid = blk * THREADS + t;

        float s0 = 0.0f, s1 = 0.0f, s2 = 0.0f, s3 = 0.0f;
        #pragma unroll 4
        for (int i = tid; i < VEC; i += SSTRIDE) {
            float4 v = cp[i];
            float p0 = fminf(fmaxf(v.x, 1e-4f), 1.0f - 1e-4f);
            float p1 = fminf(fmaxf(v.y, 1e-4f), 1.0f - 1e-4f);
            float p2 = fminf(fmaxf(v.z, 1e-4f), 1.0f - 1e-4f);
            float p3 = fminf(fmaxf(v.w, 1e-4f), 1.0f - 1e-4f);
            float l0 = __logf(1.0f - p0);
            float l1 = __logf(1.0f - p1);
            float l2 = __logf(1.0f - p2);
            float l3 = __logf(1.0f - p3);
            s0 = fmaf(p0 * p0 * l0, -0.75f, s0);
            s1 = fmaf(p1 * p1 * l1, -0.75f, s1);
            s2 = fmaf(p2 * p2 * l2, -0.75f, s2);
            s3 = fmaf(p3 * p3 * l3, -0.75f, s3);
        }
        block_reduce_commit((s0 + s1) + (s2 + s3), 0.0f, 0, b, s_c, s_r, s_p);
        return;
    }

    // ================= ASSIGN: IoU argmax + reg loss + sparse cls correction =================
    const int b    = idx / NA_TILES;
    const int tile = idx - b * NA_TILES;

    if (t < NM) {
        float4 bx = ((const float4*)boxes)[b * NM + t];
        int lab   = labels[b * NM + t];
        if (lab == 0) {                          // degenerate: inter clamps to 0
            bx = make_float4(3e9f, 3e9f, -3e9f, -3e9f);
            s_barea[t] = 0.0f;
        } else {
            s_barea[t] = (bx.z - bx.x) * (bx.w - bx.y);
        }
        s_box[t] = bx;
        s_lab[t] = lab;
    }
    __syncthreads();

    const int a = tile * THREADS + t;
    float my_reg = 0.0f, my_corr = 0.0f;
    int   my_pos = 0;

    if (a < NA) {
        float4 an = ((const float4*)anchors)[a];   // y1,x1,y2,x2
        const float ay1 = an.x, ax1 = an.y, ay2 = an.z, ax2 = an.w;
        const float a_area = (ay2 - ay1) * (ax2 - ax1);

        // division-free argmax: track (inter, ua) of the running best ratio
        float best_i = -1.0f, best_u = 1.0f; int bi = 0;
        #pragma unroll 16
        for (int m = 0; m < NM; m++) {
            float4 bx = s_box[m];                  // x1,y1,x2,y2
            float iw = fminf(ax2, bx.z) - fmaxf(ax1, bx.x);
            float ih = fminf(ay2, bx.w) - fmaxf(ay1, bx.y);
            iw = fmaxf(iw, 0.0f); ih = fmaxf(ih, 0.0f);
            float inter = iw * ih;
            float ua = fmaxf(a_area + s_barea[m] - inter, 1e-8f);
            if (inter * best_u > best_i * ua) {    // strict >: first max
                best_i = inter; best_u = ua; bi = m;
            }
        }
        float iou_max = best_i / best_u;           // exact IEEE divide, once per anchor

        float4 ab = s_box[bi];
        float  bw = ab.z - ab.x, bh = ab.w - ab.y;
        bool   big = (bw * bh) > 100.0f;
        bool   pos = big ? (iou_max >= 0.5f) : (iou_max >= 0.15f);

        if (pos) {
            my_pos = 1;
            // --- regression smooth-L1 ---
            float gcx = ab.x + 0.5f * bw, gcy = ab.y + 0.5f * bh;
            float gw = fmaxf(bw, 1.0f), gh = fmaxf(bh, 1.0f);
            float aw = ax2 - ax1, ah = ay2 - ay1;
            float acx = ax1 + 0.5f * aw, acy = ay1 + 0.5f * ah;
            float tt0 = (gcy - acy) / ah;
            float tt1 = (gcx - acx) / aw;
            float tt2 = logf(gh / ah);
            float tt3 = logf(gw / aw);
            float4 r = ((const float4*)reg)[(size_t)b * NA + a];
            float d;
            d = fabsf(tt0 - r.x); my_reg += (d <= 1.0f/9.0f) ? 4.5f*d*d : d - 0.5f/9.0f;
            d = fabsf(tt1 - r.y); my_reg += (d <= 1.0f/9.0f) ? 4.5f*d*d : d - 0.5f/9.0f;
            d = fabsf(tt2 - r.z); my_reg += (d <= 1.0f/9.0f) ? 4.5f*d*d : d - 0.5f/9.0f;
            d = fabsf(tt3 - r.w); my_reg += (d <= 1.0f/9.0f) ? 4.5f*d*d : d - 0.5f/9.0f;

            // --- sparse cls correction for the target class (stream added neg term) ---
            int al = s_lab[bi] - 1;                // in [0, NC)
            float v = cls[((size_t)b * NA + a) * NC + al];
            float p = fminf(fmaxf(v, 1e-4f), 1.0f - 1e-4f);
            float om = 1.0f - p;
            float pos_term = 0.25f * om * om * (-__logf(p));
            float neg_term = 0.75f * p  * p  * (-__logf(om));
            my_corr = pos_term - neg_term;
        }
    }
    block_reduce_commit(my_corr, my_reg, my_pos, b, s_c, s_r, s_p);
}

__global__ void fl_finalize_kernel(float* __restrict__ out) {
    int i = threadIdx.x;
    double c = 0.0, r = 0.0;
    if (i < NB) {
        int np = g_npos[i];
        double den = (double)(np > 1 ? np : 1);
        c = g_cls[i] / den;
        r = (np > 0) ? (g_reg[i] / (4.0 * den)) : 0.0;
        g_cls[i] = 0.0; g_reg[i] = 0.0; g_npos[i] = 0;   // reset for next replay
    }
    #pragma unroll
    for (int o = 16; o; o >>= 1) {
        c += __shfl_down_sync(0xFFFFFFFFu, c, o);
        r += __shfl_down_sync(0xFFFFFFFFu, r, o);
    }
    if (i == 0) {
        out[0] = (float)(c / (double)NB);
        out[1] = (float)(r / (double)NB * 50.0);
    }
}

extern "C" void kernel_launch(void* const* d_in, const int* in_sizes, int n_in,
                              void* d_out, int out_size) {
    const float* boxes   = (const float*)d_in[0];
    const int*   labels  = (const int*)  d_in[1];
    const float* anchors = (const float*)d_in[2];
    const float* cls     = (const float*)d_in[3];
    const float* reg     = (const float*)d_in[4];
    float* out = (float*)d_out;

    fl_fused_kernel<<<TOTB, THREADS>>>(boxes, labels, anchors, cls, reg);
    fl_finalize_kernel<<<1, 32>>>(out);
}